// round 10
// baseline (speedup 1.0000x reference)
#include <cuda_runtime.h>
#include <cstdint>

#define S_LEN 2048
#define BATCH 32
#define IDIM  256
#define HDIM  512
#define CL    8            // cluster size
#define THREADS_R 256

typedef unsigned long long ull;

// ---------------- PTX helpers ----------------
__device__ __forceinline__ ull pack2(float x, float y) {
    ull r; asm("mov.b64 %0, {%1, %2};" : "=l"(r) : "f"(x), "f"(y)); return r;
}
__device__ __forceinline__ void unpack2(ull v, float &x, float &y) {
    asm("mov.b64 {%0, %1}, %2;" : "=f"(x), "=f"(y) : "l"(v));
}
__device__ __forceinline__ void ffma2(ull &d, ull a, ull b) {
    asm("fma.rn.f32x2 %0, %1, %2, %0;" : "+l"(d) : "l"(a), "l"(b));
}
__device__ __forceinline__ uint32_t smem_u32(const void* p) {
    return (uint32_t)__cvta_generic_to_shared(p);
}
__device__ __forceinline__ uint32_t mapa_addr(uint32_t laddr, uint32_t rank) {
    uint32_t raddr;
    asm("mapa.shared::cluster.u32 %0, %1, %2;" : "=r"(raddr) : "r"(laddr), "r"(rank));
    return raddr;
}
// 16B remote (dsmem) load, broadcast-friendly
__device__ __forceinline__ void lds_cluster_v2(uint32_t addr, ull &a, ull &b) {
    asm volatile("ld.shared::cluster.v2.u64 {%0, %1}, [%2];"
                 : "=l"(a), "=l"(b) : "r"(addr));
}
__device__ __forceinline__ void mbar_init(uint32_t mbar, uint32_t cnt) {
    asm volatile("mbarrier.init.shared.b64 [%0], %1;" :: "r"(mbar), "r"(cnt) : "memory");
}
// plain count arrive on (possibly remote) cluster barrier, release at cluster scope
__device__ __forceinline__ void mbar_arrive_cluster(uint32_t raddr) {
    asm volatile("mbarrier.arrive.release.cluster.shared::cluster.b64 _, [%0];"
                 :: "r"(raddr) : "memory");
}
// parity wait with cluster-scope acquire (orders peers' generic STS before our LDS)
__device__ __forceinline__ void mbar_wait_cl(uint32_t mbar, uint32_t parity) {
    uint32_t done;
    asm volatile("{\n\t.reg .pred p;\n\t"
                 "mbarrier.try_wait.parity.acquire.cluster.shared::cta.b64 p, [%1], %2;\n\t"
                 "selp.b32 %0, 1, 0, p;\n\t}"
                 : "=r"(done) : "r"(mbar), "r"(parity) : "memory");
    if (!done) {
        asm volatile("{\n\t.reg .pred P1;\n\t"
                     "WL%=:\n\t"
                     "mbarrier.try_wait.parity.acquire.cluster.shared::cta.b64 P1, [%0], %1, 0x989680;\n\t"
                     "@P1 bra.uni WD%=;\n\t"
                     "bra.uni WL%=;\n\t"
                     "WD%=:\n\t}"
                     :: "r"(mbar), "r"(parity) : "memory");
    }
}
__device__ __forceinline__ void cluster_sync_() {
    asm volatile("barrier.cluster.arrive.aligned;" ::: "memory");
    asm volatile("barrier.cluster.wait.aligned;"   ::: "memory");
}

// =====================================================================
// Phase 1: z = inputs @ Wih^T + (bih + bhh), in-place into d_out.
// (unchanged from best passing version)
// =====================================================================
#define BM 64
#define BN 64
#define BK 32

__global__ __launch_bounds__(256) void zproj_kernel(
    const float* __restrict__ A, const float* __restrict__ W,
    const float* __restrict__ bih, const float* __restrict__ bhh,
    float* __restrict__ C)
{
    __shared__ __align__(16) float As[BK][BM + 8];
    __shared__ __align__(16) float Bs[BK][BN + 8];
    const int tid = threadIdx.x;
    const int m0 = blockIdx.x * BM;
    const int n0 = blockIdx.y * BN;
    const int tx = tid & 15;
    const int ty = tid >> 4;
    ull acc01[4] = {0,0,0,0};
    ull acc23[4] = {0,0,0,0};

    for (int k0 = 0; k0 < IDIM; k0 += BK) {
        #pragma unroll
        for (int i = 0; i < 2; i++) {
            int s  = tid + i * 256;
            int m  = s >> 3;
            int kq = (s & 7) << 2;
            float4 a = *(const float4*)(A + (size_t)(m0 + m) * IDIM + k0 + kq);
            As[kq+0][m] = a.x; As[kq+1][m] = a.y; As[kq+2][m] = a.z; As[kq+3][m] = a.w;
            float4 b = *(const float4*)(W + (size_t)(n0 + m) * IDIM + k0 + kq);
            Bs[kq+0][m] = b.x; Bs[kq+1][m] = b.y; Bs[kq+2][m] = b.z; Bs[kq+3][m] = b.w;
        }
        __syncthreads();
        #pragma unroll
        for (int k = 0; k < BK; k++) {
            float4 a4 = *(const float4*)&As[k][ty * 4];
            const ull* bp = (const ull*)&Bs[k][tx * 4];
            ull b01 = bp[0], b23 = bp[1];
            ull a0 = pack2(a4.x, a4.x);
            ull a1 = pack2(a4.y, a4.y);
            ull a2 = pack2(a4.z, a4.z);
            ull a3 = pack2(a4.w, a4.w);
            ffma2(acc01[0], a0, b01); ffma2(acc23[0], a0, b23);
            ffma2(acc01[1], a1, b01); ffma2(acc23[1], a1, b23);
            ffma2(acc01[2], a2, b01); ffma2(acc23[2], a2, b23);
            ffma2(acc01[3], a3, b01); ffma2(acc23[3], a3, b23);
        }
        __syncthreads();
    }

    float bias[4];
    #pragma unroll
    for (int j = 0; j < 4; j++)
        bias[j] = bih[n0 + tx * 4 + j] + bhh[n0 + tx * 4 + j];

    #pragma unroll
    for (int i = 0; i < 4; i++) {
        float4 o;
        unpack2(acc01[i], o.x, o.y);
        unpack2(acc23[i], o.z, o.w);
        o.x += bias[0]; o.y += bias[1]; o.z += bias[2]; o.w += bias[3];
        *(float4*)(C + (size_t)(m0 + ty * 4 + i) * HDIM + n0 + tx * 4) = o;
    }
}

// =====================================================================
// Phase 2: PULL-based persistent cluster scan.
// h is DISTRIBUTED: CTA rank r keeps only its 64 rows (x2 batches) in a
// tiny local double buffer. Warp w of every CTA reads k-chunk w directly
// from owner CTA w's buffer via mapa + ld.shared::cluster (all lanes
// broadcast the same address -> 1 DSMEM transaction per 16B).
// Lane l of warp w holds W rows {2l,2l+1} x k[64w..64w+64) in registers.
// Cross-warp reduce of the 8 k-chunk partials goes through smem.
// Sync per step: 2x __syncthreads + 8 remote mbarrier.arrive (lanes 0-7,
// release.cluster) + 1 try_wait.acquire.cluster on a count barrier.
// No staging, no fence.proxy.async, no bulk engine, no tx accounting.
// =====================================================================
__global__ void __cluster_dims__(CL, 1, 1) __launch_bounds__(THREADS_R, 1)
rnn_scan_kernel(const float* __restrict__ Whh,
                const float* __restrict__ h0,
                float* __restrict__ out)
{
    __shared__ __align__(16) float hbuf[2][2][64];   // [buf][batch][row] (own 64 rows only)
    __shared__ __align__(16) float red[8][132];      // [warp(kchunk)][batch*64 + row] (+pad)
    __shared__ __align__(8)  ull mbarS[2];           // count barriers (8 arrivals each)

    const int tid = threadIdx.x;
    const int w   = tid >> 5;            // warp = k-chunk = owner rank to read from
    const int l   = tid & 31;            // lane = rowpair (rows 2l, 2l+1)
    uint32_t rank; asm("mov.u32 %0, %%cluster_ctarank;" : "=r"(rank));
    const int b0 = (blockIdx.x / CL) * 2;

    const uint32_t mloc = smem_u32(&mbarS[0]);
    const uint32_t hloc = smem_u32(&hbuf[0][0][0]);

    // ---- W slice into regs: rows {2l, 2l+1}, k in [64w, 64w+64) ----
    const int grow0 = (int)rank * 64 + 2 * l;
    const ull* wr0 = (const ull*)(Whh + (size_t)grow0 * HDIM + w * 64);
    const ull* wr1 = wr0 + (HDIM / 2);
    ull w2a[32], w2b[32];
    #pragma unroll
    for (int j = 0; j < 32; j++) { w2a[j] = wr0[j]; w2b[j] = wr1[j]; }

    // ---- remote base for this warp's owner CTA ----
    const uint32_t rbase = mapa_addr(hloc, (uint32_t)w);

    // ---- init: own h0 rows into buf 0; count barriers ----
    if (tid < 128) {
        int pb = tid >> 6, rr = tid & 63;
        hbuf[0][pb][rr] = h0[(size_t)(b0 + pb) * HDIM + (size_t)rank * 64 + rr];
    }
    if (tid == 0) {
        mbar_init(mloc,     CL);
        mbar_init(mloc + 8, CL);
    }
    // arrive targets: lane r (tid<8) arrives on rank r's barriers
    uint32_t arr_base = 0;
    if (tid < CL) arr_base = mapa_addr(mloc, (uint32_t)tid);
    __syncthreads();
    cluster_sync_();   // peers' buf0 + barrier inits visible cluster-wide

    // ---- reducer identity (tid < 128): (batch pb, row rr) ----
    size_t zoff = 0, foff = 0;
    float z_cur = 0.f;
    int pb = 0, rr = 0;
    if (tid < 128) {
        pb = tid >> 6; rr = tid & 63;
        zoff = ((size_t)(b0 + pb) * S_LEN) * HDIM + (size_t)rank * 64 + rr;
        foff = (size_t)BATCH * S_LEN * HDIM + (size_t)(b0 + pb) * HDIM + (size_t)rank * 64 + rr;
        z_cur = out[zoff];                 // z[t=0] prefetch
    }

    uint32_t p0 = 0, p1 = 0;
    for (int t = 0; t < S_LEN; t++) {
        const int cur = t & 1;
        // prefetch z_{t+1} (last iter reads in-bounds tail region)
        float z_next = z_cur;
        if (tid < 128) z_next = out[zoff + HDIM];

        if (t > 0) {
            if (cur) { mbar_wait_cl(mloc + 8, p1); p1 ^= 1; }
            else     { mbar_wait_cl(mloc,     p0); p0 ^= 1; }
        }

        // ---- matvec partials over k-chunk w, read from owner CTA w ----
        const uint32_t rb0 = rbase + (uint32_t)cur * 512u;        // batch0 floats
        const uint32_t rb1 = rb0 + 256u;                          // batch1
        ull aA0 = 0, aA1 = 0, aB0 = 0, aB1 = 0;
        #pragma unroll
        for (int j2 = 0; j2 < 16; j2++) {
            ull p0v, p1v, q0v, q1v;
            lds_cluster_v2(rb0 + j2 * 16u, p0v, p1v);   // h[2k..2k+3] batch0
            lds_cluster_v2(rb1 + j2 * 16u, q0v, q1v);   // batch1
            ffma2(aA0, w2a[2*j2],   p0v);
            ffma2(aA1, w2b[2*j2],   p0v);
            ffma2(aB0, w2a[2*j2],   q0v);
            ffma2(aB1, w2b[2*j2],   q0v);
            ffma2(aA0, w2a[2*j2+1], p1v);
            ffma2(aA1, w2b[2*j2+1], p1v);
            ffma2(aB0, w2a[2*j2+1], q0v ^ q0v ^ q1v);   // q1v (defeat nothing; plain)
            ffma2(aB1, w2b[2*j2+1], q1v);
        }
        float x, y, pA0, pA1, pB0, pB1;
        unpack2(aA0, x, y); pA0 = x + y;    // row 2l, batch0 partial
        unpack2(aA1, x, y); pA1 = x + y;    // row 2l+1, batch0
        unpack2(aB0, x, y); pB0 = x + y;    // row 2l, batch1
        unpack2(aB1, x, y); pB1 = x + y;

        // write partials: red[w][pb*64 + row]
        *(float2*)&red[w][2*l]      = make_float2(pA0, pA1);
        *(float2*)&red[w][64 + 2*l] = make_float2(pB0, pB1);
        __syncthreads();

        if (tid < 128) {
            float s = z_cur;
            #pragma unroll
            for (int q = 0; q < 8; q++) s += red[q][pb * 64 + rr];
            float v = fmaxf(s, 0.f);
            out[zoff] = v;                        // h_t overwrites z_t
            if (t == S_LEN - 1) out[foff] = v;
            hbuf[cur ^ 1][pb][rr] = v;            // own chunk, next buffer
            z_cur = z_next;
            zoff += HDIM;
        }
        __syncthreads();   // buf[nxt] fully written before signaling

        if (tid < CL && t < S_LEN - 1)
            mbar_arrive_cluster(arr_base + (uint32_t)(cur ^ 1) * 8u);
    }
}

// =====================================================================
extern "C" void kernel_launch(void* const* d_in, const int* in_sizes, int n_in,
                              void* d_out, int out_size) {
    (void)in_sizes; (void)n_in; (void)out_size;
    const float* inputs = (const float*)d_in[0];
    const float* h0     = (const float*)d_in[1];
    const float* Wih    = (const float*)d_in[2];
    const float* Whh    = (const float*)d_in[3];
    const float* bih    = (const float*)d_in[4];
    const float* bhh    = (const float*)d_in[5];
    float* out = (float*)d_out;

    dim3 g1((BATCH * S_LEN) / BM, HDIM / BN);
    zproj_kernel<<<g1, 256>>>(inputs, Wih, bih, bhh, out);
    rnn_scan_kernel<<<(BATCH / 2) * CL, THREADS_R>>>(Whh, h0, out);
}

// round 11
// speedup vs baseline: 1.3584x; 1.3584x over previous
#include <cuda_runtime.h>
#include <cstdint>

#define S_LEN 2048
#define BATCH 32
#define IDIM  256
#define HDIM  512
#define CL    8            // cluster size
#define THREADS_R 256

typedef unsigned long long ull;

// ---------------- PTX helpers ----------------
__device__ __forceinline__ ull pack2(float x, float y) {
    ull r; asm("mov.b64 %0, {%1, %2};" : "=l"(r) : "f"(x), "f"(y)); return r;
}
__device__ __forceinline__ void unpack2(ull v, float &x, float &y) {
    asm("mov.b64 {%0, %1}, %2;" : "=f"(x), "=f"(y) : "l"(v));
}
__device__ __forceinline__ void ffma2(ull &d, ull a, ull b) {
    asm("fma.rn.f32x2 %0, %1, %2, %0;" : "+l"(d) : "l"(a), "l"(b));
}
__device__ __forceinline__ uint32_t smem_u32(const void* p) {
    return (uint32_t)__cvta_generic_to_shared(p);
}
__device__ __forceinline__ uint32_t mapa_addr(uint32_t laddr, uint32_t rank) {
    uint32_t raddr;
    asm("mapa.shared::cluster.u32 %0, %1, %2;" : "=r"(raddr) : "r"(laddr), "r"(rank));
    return raddr;
}
// plain 4B remote smem store (fire-and-forget, no mbarrier coupling)
__device__ __forceinline__ void st_cluster_f32(uint32_t raddr, float v) {
    asm volatile("st.shared::cluster.b32 [%0], %1;"
                 :: "r"(raddr), "r"(__float_as_uint(v)) : "memory");
}
__device__ __forceinline__ void mbar_init(uint32_t mbar, uint32_t cnt) {
    asm volatile("mbarrier.init.shared.b64 [%0], %1;" :: "r"(mbar), "r"(cnt) : "memory");
}
// count arrive on remote cluster barrier, release at cluster scope
__device__ __forceinline__ void mbar_arrive_cluster(uint32_t raddr) {
    asm volatile("mbarrier.arrive.release.cluster.shared::cluster.b64 _, [%0];"
                 :: "r"(raddr) : "memory");
}
// parity wait with cluster-scope acquire
__device__ __forceinline__ void mbar_wait_cl(uint32_t mbar, uint32_t parity) {
    uint32_t done;
    asm volatile("{\n\t.reg .pred p;\n\t"
                 "mbarrier.try_wait.parity.acquire.cluster.shared::cta.b64 p, [%1], %2;\n\t"
                 "selp.b32 %0, 1, 0, p;\n\t}"
                 : "=r"(done) : "r"(mbar), "r"(parity) : "memory");
    if (!done) {
        asm volatile("{\n\t.reg .pred P1;\n\t"
                     "WL%=:\n\t"
                     "mbarrier.try_wait.parity.acquire.cluster.shared::cta.b64 P1, [%0], %1, 0x989680;\n\t"
                     "@P1 bra.uni WD%=;\n\t"
                     "bra.uni WL%=;\n\t"
                     "WD%=:\n\t}"
                     :: "r"(mbar), "r"(parity) : "memory");
    }
}
__device__ __forceinline__ void cluster_sync_() {
    asm volatile("barrier.cluster.arrive.aligned;" ::: "memory");
    asm volatile("barrier.cluster.wait.aligned;"   ::: "memory");
}

// =====================================================================
// Phase 1: z = inputs @ Wih^T + (bih + bhh), in-place into d_out.
// (unchanged — f32x2 packed inner product)
// =====================================================================
#define BM 64
#define BN 64
#define BK 32

__global__ __launch_bounds__(256) void zproj_kernel(
    const float* __restrict__ A, const float* __restrict__ W,
    const float* __restrict__ bih, const float* __restrict__ bhh,
    float* __restrict__ C)
{
    __shared__ __align__(16) float As[BK][BM + 8];
    __shared__ __align__(16) float Bs[BK][BN + 8];
    const int tid = threadIdx.x;
    const int m0 = blockIdx.x * BM;
    const int n0 = blockIdx.y * BN;
    const int tx = tid & 15;
    const int ty = tid >> 4;
    ull acc01[4] = {0,0,0,0};
    ull acc23[4] = {0,0,0,0};

    for (int k0 = 0; k0 < IDIM; k0 += BK) {
        #pragma unroll
        for (int i = 0; i < 2; i++) {
            int s  = tid + i * 256;
            int m  = s >> 3;
            int kq = (s & 7) << 2;
            float4 a = *(const float4*)(A + (size_t)(m0 + m) * IDIM + k0 + kq);
            As[kq+0][m] = a.x; As[kq+1][m] = a.y; As[kq+2][m] = a.z; As[kq+3][m] = a.w;
            float4 b = *(const float4*)(W + (size_t)(n0 + m) * IDIM + k0 + kq);
            Bs[kq+0][m] = b.x; Bs[kq+1][m] = b.y; Bs[kq+2][m] = b.z; Bs[kq+3][m] = b.w;
        }
        __syncthreads();
        #pragma unroll
        for (int k = 0; k < BK; k++) {
            float4 a4 = *(const float4*)&As[k][ty * 4];
            const ull* bp = (const ull*)&Bs[k][tx * 4];
            ull b01 = bp[0], b23 = bp[1];
            ull a0 = pack2(a4.x, a4.x);
            ull a1 = pack2(a4.y, a4.y);
            ull a2 = pack2(a4.z, a4.z);
            ull a3 = pack2(a4.w, a4.w);
            ffma2(acc01[0], a0, b01); ffma2(acc23[0], a0, b23);
            ffma2(acc01[1], a1, b01); ffma2(acc23[1], a1, b23);
            ffma2(acc01[2], a2, b01); ffma2(acc23[2], a2, b23);
            ffma2(acc01[3], a3, b01); ffma2(acc23[3], a3, b23);
        }
        __syncthreads();
    }

    float bias[4];
    #pragma unroll
    for (int j = 0; j < 4; j++)
        bias[j] = bih[n0 + tx * 4 + j] + bhh[n0 + tx * 4 + j];

    #pragma unroll
    for (int i = 0; i < 4; i++) {
        float4 o;
        unpack2(acc01[i], o.x, o.y);
        unpack2(acc23[i], o.z, o.w);
        o.x += bias[0]; o.y += bias[1]; o.z += bias[2]; o.w += bias[3];
        *(float4*)(C + (size_t)(m0 + ty * 4 + i) * HDIM + n0 + tx * 4) = o;
    }
}

// =====================================================================
// Phase 2: PUSH with plain remote stores + per-source count barriers.
// 16 clusters x 8 CTAs; cluster owns 2 batches; CTA rank s computes h
// rows [64s, 64s+64) (W slice in regs, k-pair packed f32x2).
// Full h kept LOCAL per CTA (hbuf[2][2][512]); producers scatter their
// 128 values (2 batches x 64 rows) to all 8 ranks via plain 4B
// st.shared::cluster (distinct addresses -> no serialization point),
// then __syncthreads, then lanes 0..7 do ONE count-arrive each
// (release.cluster) at rank r's per-source barrier mbar[nxt][s].
// Consumers: warp w (k-chunk w, i.e. source rows 64w..64w+64) waits only
// on mbar[cur][w] -> per-source decoupling absorbs CTA skew; matvec
// reads broadcast LOCAL smem. No tx accounting, no bulk engine, no
// st.async, no fence.proxy.
// =====================================================================
__global__ void __cluster_dims__(CL, 1, 1) __launch_bounds__(THREADS_R, 1)
rnn_scan_kernel(const float* __restrict__ Whh,
                const float* __restrict__ h0,
                float* __restrict__ out)
{
    __shared__ __align__(16) float hbuf[2][2][HDIM];   // [buf][batch][row], full local h
    __shared__ __align__(16) float red[8][132];        // [warp(kchunk)][batch*64+row] (+pad)
    __shared__ __align__(8)  ull mbarS[2][CL];         // [buf][src], count=1 each

    const int tid = threadIdx.x;
    const int w   = tid >> 5;            // warp = k-chunk = source rank whose rows it consumes
    const int l   = tid & 31;            // lane = rowpair (rows 2l, 2l+1 of own slice)
    uint32_t rank; asm("mov.u32 %0, %%cluster_ctarank;" : "=r"(rank));
    const int b0 = (blockIdx.x / CL) * 2;

    const uint32_t mloc = smem_u32(&mbarS[0][0]);
    const uint32_t hloc = smem_u32(&hbuf[0][0][0]);

    // ---- W slice into regs: rows {rank*64+2l, +1}, k in [64w, 64w+64) ----
    const int grow0 = (int)rank * 64 + 2 * l;
    const ull* wr0 = (const ull*)(Whh + (size_t)grow0 * HDIM + w * 64);
    const ull* wr1 = wr0 + (HDIM / 2);
    ull w2a[32], w2b[32];
    #pragma unroll
    for (int j = 0; j < 32; j++) { w2a[j] = wr0[j]; w2b[j] = wr1[j]; }

    // ---- init: FULL h0 (both batches) into local buf 0; barriers ----
    for (int g = tid; g < HDIM; g += THREADS_R) {
        hbuf[0][0][g] = h0[(size_t)b0 * HDIM + g];
        hbuf[0][1][g] = h0[(size_t)(b0 + 1) * HDIM + g];
    }
    if (tid < 2 * CL) mbar_init(mloc + tid * 8u, 1);
    __syncthreads();
    cluster_sync_();   // barrier inits visible cluster-wide before any remote arrive

    // ---- reducer identity (tid < 128): (batch pb, own-slice row rr) ----
    size_t zoff = 0, foff = 0;
    float z_cur = 0.f;
    int pb = 0, rr = 0;
    uint32_t rbh[CL];                // remote hbuf bases (for pushes)
    if (tid < 128) {
        pb = tid >> 6; rr = tid & 63;
        const int grow = (int)rank * 64 + rr;
        zoff = ((size_t)(b0 + pb) * S_LEN) * HDIM + grow;
        foff = (size_t)BATCH * S_LEN * HDIM + (size_t)(b0 + pb) * HDIM + grow;
        z_cur = out[zoff];           // z[t=0] prefetch
        #pragma unroll
        for (uint32_t r = 0; r < CL; r++) rbh[r] = mapa_addr(hloc, r);
    }
    // push byte offset within a buffer: (pb*512 + rank*64 + rr) * 4
    const uint32_t pushoff = (uint32_t)(pb * HDIM + (int)rank * 64 + rr) * 4u;

    // ---- arrive targets: lane r arrives at rank r's mbar[nxt][myrank] ----
    uint32_t arrA = 0;
    if (tid < CL) arrA = mapa_addr(mloc, (uint32_t)tid) + rank * 8u;

    uint32_t p0 = 0, p1 = 0;        // per-warp parities for buf0/buf1 source barrier
    for (int t = 0; t < S_LEN; t++) {
        const int cur = t & 1;
        const int nxt = cur ^ 1;
        // prefetch z_{t+1} (last iter reads in-bounds tail region)
        float z_next = z_cur;
        if (tid < 128) z_next = out[zoff + HDIM];

        if (t > 0) {   // warp w waits only for source CTA w's slice of buf[cur]
            if (cur) { mbar_wait_cl(mloc + (8 + w) * 8u, p1); p1 ^= 1; }
            else     { mbar_wait_cl(mloc + w * 8u,       p0); p0 ^= 1; }
        }

        // ---- matvec partials over k-chunk w, LOCAL broadcast reads ----
        const ull* hb0 = (const ull*)&hbuf[cur][0][w * 64];
        const ull* hb1 = (const ull*)&hbuf[cur][1][w * 64];
        ull aA0 = 0, aA1 = 0, aB0 = 0, aB1 = 0;
        #pragma unroll
        for (int j = 0; j < 32; j++) {
            ull h0v = hb0[j];
            ull h1v = hb1[j];
            ffma2(aA0, w2a[j], h0v);   // row 2l,   batch0
            ffma2(aA1, w2b[j], h0v);   // row 2l+1, batch0
            ffma2(aB0, w2a[j], h1v);   // row 2l,   batch1
            ffma2(aB1, w2b[j], h1v);   // row 2l+1, batch1
        }
        float x, y, pA0, pA1, pB0, pB1;
        unpack2(aA0, x, y); pA0 = x + y;
        unpack2(aA1, x, y); pA1 = x + y;
        unpack2(aB0, x, y); pB0 = x + y;
        unpack2(aB1, x, y); pB1 = x + y;

        *(float2*)&red[w][2*l]      = make_float2(pA0, pA1);
        *(float2*)&red[w][64 + 2*l] = make_float2(pB0, pB1);
        __syncthreads();

        if (tid < 128) {
            float s = z_cur;
            #pragma unroll
            for (int q = 0; q < 8; q++) s += red[q][pb * 64 + rr];
            float v = fmaxf(s, 0.f);
            out[zoff] = v;                          // h_t overwrites z_t
            if (t == S_LEN - 1) out[foff] = v;
            if (t < S_LEN - 1) {
                const uint32_t off = (uint32_t)nxt * 4096u + pushoff;
                #pragma unroll
                for (int r = 0; r < CL; r++)        // scatter to all ranks (incl. self)
                    st_cluster_f32(rbh[r] + off, v);
            }
            z_cur = z_next;
            zoff += HDIM;
        }
        __syncthreads();   // all pushes issued, CTA-cumulative before release-arrive

        if (tid < CL && t < S_LEN - 1)
            mbar_arrive_cluster(arrA + (uint32_t)nxt * (CL * 8u));
    }
    cluster_sync_();       // keep smem alive until all inbound ops consumed
}

// =====================================================================
extern "C" void kernel_launch(void* const* d_in, const int* in_sizes, int n_in,
                              void* d_out, int out_size) {
    (void)in_sizes; (void)n_in; (void)out_size;
    const float* inputs = (const float*)d_in[0];
    const float* h0     = (const float*)d_in[1];
    const float* Wih    = (const float*)d_in[2];
    const float* Whh    = (const float*)d_in[3];
    const float* bih    = (const float*)d_in[4];
    const float* bhh    = (const float*)d_in[5];
    float* out = (float*)d_out;

    dim3 g1((BATCH * S_LEN) / BM, HDIM / BN);
    zproj_kernel<<<g1, 256>>>(inputs, Wih, bih, bhh, out);
    rnn_scan_kernel<<<(BATCH / 2) * CL, THREADS_R>>>(Whh, h0, out);
}